// round 4
// baseline (speedup 1.0000x reference)
#include <cuda_runtime.h>
#include <cuda_bf16.h>

#define TT 2048
#define CC 64
#define EE 16
#define ROWS_PER_THREAD 2
#define NTL 4                       // tl groups per block (1 per warp)
#define TB (NTL*ROWS_PER_THREAD)    // 8 t-rows per block
#define NPART 2
#define NTHREADS (EE*NPART*NTL)     // 128
#define EPSF 1e-6f
// logf(1e-6f) - log1pf(-1e-6f)
#define LOGIT_EPS (-13.815510f)

#define RED2(v) v += __shfl_xor_sync(0xffffffffu, v, 16);

__global__ __launch_bounds__(NTHREADS, 4)
void role_learner_kernel(const float* __restrict__ pbar,
                         const float* __restrict__ rho_dir,
                         const float* __restrict__ rho_ind,
                         const float* __restrict__ gamma_dir,
                         const float* __restrict__ gamma_ind,
                         const float* __restrict__ gamma_ctr,
                         const float* __restrict__ bias,
                         float* __restrict__ out)
{
    __shared__ float sp [TB * CC];   // p tile   [TB][C]
    __shared__ float srd[CC * EE];   // rho_dir  [C][E], clipped
    __shared__ float sri[CC * EE];   // rho_ind  [C][E], clipped

    const int tid = threadIdx.x;
    const int t0  = blockIdx.x * TB;

    // float4 staging: p tile (TB*CC = 512 floats = 128 float4)
    {
        const float4* src = (const float4*)(pbar + t0 * CC);
        float4* dst = (float4*)sp;
        if (tid < (TB * CC) / 4) dst[tid] = src[tid];
    }
    // rho tiles: 1024 floats = 256 float4 each; 2 per thread per array
    {
        const float4* s0 = (const float4*)rho_dir;
        const float4* s1 = (const float4*)rho_ind;
        float4* d0 = (float4*)srd;
        float4* d1 = (float4*)sri;
        #pragma unroll
        for (int i = tid; i < (CC * EE) / 4; i += NTHREADS) {
            float4 v = s0[i];
            v.x = __saturatef(v.x); v.y = __saturatef(v.y);
            v.z = __saturatef(v.z); v.w = __saturatef(v.w);
            d0[i] = v;
            float4 w = s1[i];
            w.x = __saturatef(w.x); w.y = __saturatef(w.y);
            w.z = __saturatef(w.z); w.w = __saturatef(w.w);
            d1[i] = w;
        }
    }
    __syncthreads();

    // lane bits: [3:0]=e, [4]=part ; thread bits [6:5]=tl (one tl per warp)
    const int e    = tid & (EE - 1);
    const int part = (tid >> 4) & 1;
    const int tl   = tid >> 5;
    const float* prow0 = &sp[(2 * tl + 0) * CC];
    const float* prow1 = &sp[(2 * tl + 1) * CC];

    // Two independent accumulator sets (rows r0, r1)
    float A1=0.f,A2=0.f,A3=0.f,A4=0.f,A5=0.f,A6=0.f,A7=0.f,A8=0.f, prodA=1.f;
    float B1=0.f,B2=0.f,B3=0.f,B4=0.f,B5=0.f,B6=0.f,B7=0.f,B8=0.f, prodB=1.f;

    #pragma unroll
    for (int j = 0; j < CC / NPART; j++) {
        const int c  = 2 * j + part;
        const float rd = srd[c * EE + e];   // banks: e + 16*part -> conflict-free
        const float ri = sri[c * EE + e];
        const float pa = prow0[c];
        const float pb = prow1[c];

        prodA *= fmaxf(fmaf(-pa, rd, 1.0f), EPSF);
        prodB *= fmaxf(fmaf(-pb, rd, 1.0f), EPSF);

        {
            const float a  = pa * ri;
            const float a2 = a  * a;
            const float a3 = a2 * a;
            const float a4 = a2 * a2;
            A1 += a;  A2 += a2;  A3 += a3;  A4 += a4;
            A5 = fmaf(a4, a,  A5);
            A6 = fmaf(a4, a2, A6);
            A7 = fmaf(a4, a3, A7);
            A8 = fmaf(a4, a4, A8);
        }
        {
            const float b  = pb * ri;
            const float b2 = b  * b;
            const float b3 = b2 * b;
            const float b4 = b2 * b2;
            B1 += b;  B2 += b2;  B3 += b3;  B4 += b4;
            B5 = fmaf(b4, b,  B5);
            B6 = fmaf(b4, b2, B6);
            B7 = fmaf(b4, b3, B7);
            B8 = fmaf(b4, b4, B8);
        }
    }

    float LDa = __logf(prodA);
    float LDb = __logf(prodB);

    // butterfly over the part bit (lane xor 16)
    RED2(LDa); RED2(LDb);
    RED2(A1); RED2(A2); RED2(A3); RED2(A4);
    RED2(A5); RED2(A6); RED2(A7); RED2(A8);
    RED2(B1); RED2(B2); RED2(B3); RED2(B4);
    RED2(B5); RED2(B6); RED2(B7); RED2(B8);

    const float gd = gamma_dir[e];
    const float gi = gamma_ind[e];
    const float gc = gamma_ctr[e];
    const float bs = bias[e];

    #pragma unroll
    for (int r = 0; r < 2; r++) {
        const float LD = r ? LDb : LDa;
        const float S1 = r ? B1 : A1, S2 = r ? B2 : A2, S3 = r ? B3 : A3,
                    S4 = r ? B4 : A4, S5 = r ? B5 : A5, S6 = r ? B6 : A6,
                    S7 = r ? B7 : A7, S8 = r ? B8 : A8;
        (void)S5; (void)S7;

        // Z = sum_{i<j} log(1 - a_i a_j) = -0.5 * sum_{k=1..4} (S_k^2 - S_{2k})/k
        const float Z = -0.5f * ( (S1*S1 - S2)
                        + 0.5f          * (S2*S2 - S4)
                        + 0.3333333433f * (S3*S3 - S6)
                        + 0.25f         * (S4*S4 - S8) );

        const float eD = __expf(LD);   // 1 - D
        const float eI = __expf(Z);    // 1 - I
        const float D  = 1.0f - eD;
        const float I  = 1.0f - eI;
        const float ctr    = eD * eI;
        const float om_ctr = fmaf(-eD, eI, 1.0f);
        const float lctr   = LD + Z;   // exact log(ctr)

        // logit with reference clipping; log(1-x) taken from the exact log-sums
        float lD;
        if (D < EPSF)       lD = LOGIT_EPS;
        else if (eD < EPSF) lD = -LOGIT_EPS;
        else                lD = __logf(D) - LD;

        float lI;
        if (I < EPSF)       lI = LOGIT_EPS;
        else if (eI < EPSF) lI = -LOGIT_EPS;
        else                lI = __logf(I) - Z;

        float lC;
        if (ctr < EPSF)          lC = LOGIT_EPS;
        else if (om_ctr < EPSF)  lC = -LOGIT_EPS;
        else                     lC = lctr - __logf(om_ctr);

        const float logits = gd * lD + gi * lI + gc * lC + bs;
        if (part == 0)
            out[(t0 + 2 * tl + r) * EE + e] = 1.0f / (1.0f + __expf(-logits));
    }
}

extern "C" void kernel_launch(void* const* d_in, const int* in_sizes, int n_in,
                              void* d_out, int out_size)
{
    (void)in_sizes; (void)n_in; (void)out_size;
    const float* pbar      = (const float*)d_in[0];
    const float* rho_dir   = (const float*)d_in[1];
    const float* rho_ind   = (const float*)d_in[2];
    // d_in[3] = rho_ctr (unused in forward)
    const float* gamma_dir = (const float*)d_in[4];
    const float* gamma_ind = (const float*)d_in[5];
    const float* gamma_ctr = (const float*)d_in[6];
    const float* bias      = (const float*)d_in[7];
    float* out = (float*)d_out;

    role_learner_kernel<<<TT / TB, NTHREADS>>>(
        pbar, rho_dir, rho_ind, gamma_dir, gamma_ind, gamma_ctr, bias, out);
}